// round 2
// baseline (speedup 1.0000x reference)
#include <cuda_runtime.h>

#define H 128
#define NMAX 100000

// Scratch (device globals: no allocation allowed in kernel_launch).
__device__ __align__(16) float g_agg[(size_t)NMAX * H];
__device__ __align__(16) float g_hid[(size_t)NMAX * H];

// ---------------------------------------------------------------------------
// Kernel 1: agg = (1+eps)*x  (eps = 0)
// ---------------------------------------------------------------------------
__global__ void init_agg_kernel(const float* __restrict__ x, int n_f4) {
    int i = blockIdx.x * blockDim.x + threadIdx.x;
    if (i < n_f4) {
        ((float4*)g_agg)[i] = ((const float4*)x)[i];
    }
}

// ---------------------------------------------------------------------------
// Kernel 2: edge scatter. One warp per edge.
//   agg[dst] += x[src] + ew * w_edge + b_edge
// Each lane handles 4 floats (float4) -> red.global.add.v4.f32
// edge_index arrives as int32 (harness downcasts the reference's int64).
// ---------------------------------------------------------------------------
__global__ void scatter_edges_kernel(const float* __restrict__ x,
                                     const int* __restrict__ ei,
                                     const float* __restrict__ ew,
                                     const float* __restrict__ w_edge,
                                     const float* __restrict__ b_edge,
                                     int E, int n) {
    int gw = (int)((blockIdx.x * (unsigned)blockDim.x + threadIdx.x) >> 5);
    int lane = threadIdx.x & 31;
    if (gw >= E) return;

    int s = __ldg(ei + gw);
    int d = __ldg(ei + (size_t)E + gw);
    // Defensive: with correct dtype these never fire (indices uniform in [0,n)).
    if ((unsigned)s >= (unsigned)n || (unsigned)d >= (unsigned)n) return;
    float w = __ldg(ew + gw);

    float4 we = __ldg((const float4*)w_edge + lane);
    float4 be = __ldg((const float4*)b_edge + lane);
    float4 xs = __ldg((const float4*)(x + (size_t)s * H) + lane);

    float4 v;
    v.x = fmaf(w, we.x, xs.x + be.x);
    v.y = fmaf(w, we.y, xs.y + be.y);
    v.z = fmaf(w, we.z, xs.z + be.z);
    v.w = fmaf(w, we.w, xs.w + be.w);

    float* dst = g_agg + (size_t)d * H + lane * 4;
    asm volatile("red.global.add.v4.f32 [%0], {%1, %2, %3, %4};"
                 :: "l"(dst), "f"(v.x), "f"(v.y), "f"(v.z), "f"(v.w)
                 : "memory");
}

// ---------------------------------------------------------------------------
// Kernel 3/4: fp32 GEMM  out[n][o] = act( sum_k in[n][k]*w[o][k] + bias[o] )
// Block: 256 threads, C tile = 64 rows x 128 cols, per-thread 8x4 register tile.
// K processed in 2 chunks of 64. Smem: W chunk transposed [64k][128col] (32KB)
// + A chunk [64row][64k] (16KB) = 48KB (static limit).
// ---------------------------------------------------------------------------
template <bool RELU>
__device__ __forceinline__ void mlp_body(const float* __restrict__ in,
                                         const float* __restrict__ w,
                                         const float* __restrict__ bias,
                                         float* __restrict__ out, int n) {
    __shared__ float ws[64][H];   // ws[k][col] for current K-chunk
    __shared__ float as[64][64];  // as[row][k]  for current K-chunk

    int row0 = blockIdx.x * 64;
    int tid = threadIdx.x;
    int tr = tid >> 5;   // 0..7  (warp id -> 8-row group)
    int tc = tid & 31;   // 0..31 (lane   -> 4-col group)

    float acc[8][4];
#pragma unroll
    for (int r = 0; r < 8; ++r)
#pragma unroll
        for (int c = 0; c < 4; ++c) acc[r][c] = 0.0f;

#pragma unroll
    for (int kc = 0; kc < 2; ++kc) {
        // --- stage W chunk: w[col][kc*64 + k], transposed into ws[k][col] ---
        // 128 cols x 16 float4 = 2048 float4, 8 per thread
#pragma unroll
        for (int i = 0; i < 8; ++i) {
            int f4 = tid + 256 * i;
            int col = f4 & 127;
            int kq = f4 >> 7;  // 0..15
            float4 v = __ldg((const float4*)(w + (size_t)col * H + kc * 64) + kq);
            ws[kq * 4 + 0][col] = v.x;
            ws[kq * 4 + 1][col] = v.y;
            ws[kq * 4 + 2][col] = v.z;
            ws[kq * 4 + 3][col] = v.w;
        }
        // --- stage A chunk: in[row0+row][kc*64 + k] into as[row][k] ---
        // 64 rows x 16 float4 = 1024 float4, 4 per thread
#pragma unroll
        for (int i = 0; i < 4; ++i) {
            int f4 = tid + 256 * i;
            int row = f4 >> 4;  // 0..63
            int kq = f4 & 15;   // 0..15
            int grow = row0 + row;
            float4 v = make_float4(0.f, 0.f, 0.f, 0.f);
            if (grow < n)
                v = __ldg((const float4*)(in + (size_t)grow * H + kc * 64) + kq);
            ((float4*)as[row])[kq] = v;
        }
        __syncthreads();

#pragma unroll
        for (int k = 0; k < 64; ++k) {
            float4 b4 = ((float4*)ws[k])[tc];  // cols tc*4 .. tc*4+3 (LDS.128, conflict-free)
            float a[8];
#pragma unroll
            for (int r = 0; r < 8; ++r) a[r] = as[tr * 8 + r][k];  // warp broadcast
#pragma unroll
            for (int r = 0; r < 8; ++r) {
                acc[r][0] = fmaf(a[r], b4.x, acc[r][0]);
                acc[r][1] = fmaf(a[r], b4.y, acc[r][1]);
                acc[r][2] = fmaf(a[r], b4.z, acc[r][2]);
                acc[r][3] = fmaf(a[r], b4.w, acc[r][3]);
            }
        }
        __syncthreads();
    }

    float4 bv = __ldg((const float4*)bias + tc);
#pragma unroll
    for (int r = 0; r < 8; ++r) {
        int grow = row0 + tr * 8 + r;
        if (grow < n) {
            float4 o;
            o.x = acc[r][0] + bv.x;
            o.y = acc[r][1] + bv.y;
            o.z = acc[r][2] + bv.z;
            o.w = acc[r][3] + bv.w;
            if (RELU) {
                o.x = fmaxf(o.x, 0.f);
                o.y = fmaxf(o.y, 0.f);
                o.z = fmaxf(o.z, 0.f);
                o.w = fmaxf(o.w, 0.f);
            }
            ((float4*)(out + (size_t)grow * H))[tc] = o;
        }
    }
}

__global__ __launch_bounds__(256) void mlp1_kernel(const float* __restrict__ w1,
                                                   const float* __restrict__ b1,
                                                   int n) {
    mlp_body<true>(g_agg, w1, b1, g_hid, n);
}

__global__ __launch_bounds__(256) void mlp2_kernel(const float* __restrict__ w2,
                                                   const float* __restrict__ b2,
                                                   float* __restrict__ out, int n) {
    mlp_body<false>(g_hid, w2, b2, out, n);
}

// ---------------------------------------------------------------------------
// Launch. Inputs (metadata order):
// 0: x [N,H] f32      1: edge_index [2,E] i32 (downcast from i64)
// 2: edge_weight [E] f32
// 3: w_edge [H] f32   4: b_edge [H] f32
// 5: w1 [H,H] f32     6: b1 [H] f32             7: w2 [H,H] f32   8: b2 [H] f32
// out: [N,H] f32
// ---------------------------------------------------------------------------
extern "C" void kernel_launch(void* const* d_in, const int* in_sizes, int n_in,
                              void* d_out, int out_size) {
    const float* x = (const float*)d_in[0];
    const int* ei = (const int*)d_in[1];
    const float* ew = (const float*)d_in[2];
    const float* w_edge = (const float*)d_in[3];
    const float* b_edge = (const float*)d_in[4];
    const float* w1 = (const float*)d_in[5];
    const float* b1 = (const float*)d_in[6];
    const float* w2 = (const float*)d_in[7];
    const float* b2 = (const float*)d_in[8];
    float* out = (float*)d_out;

    int n = in_sizes[0] / H;       // 100000
    int E = in_sizes[1] / 2;       // 1600000

    // 1) agg = x
    int n_f4 = n * (H / 4);
    init_agg_kernel<<<(n_f4 + 255) / 256, 256>>>(x, n_f4);

    // 2) scatter-add over edges (1 warp / edge)
    long long threads = (long long)E * 32;
    int blocks = (int)((threads + 255) / 256);
    scatter_edges_kernel<<<blocks, 256>>>(x, ei, ew, w_edge, b_edge, E, n);

    // 3) hid = relu(agg @ w1^T + b1)
    int gblocks = (n + 63) / 64;
    mlp1_kernel<<<gblocks, 256>>>(w1, b1, n);

    // 4) out = hid @ w2^T + b2
    mlp2_kernel<<<gblocks, 256>>>(w2, b2, out, n);
}

// round 3
// speedup vs baseline: 1.3422x; 1.3422x over previous
#include <cuda_runtime.h>

#define H 128
#define NMAX 100000
#define EMAX 1600000

typedef unsigned long long ull;

// ---------------- device scratch (no allocs allowed) ----------------
__device__ __align__(16) float g_agg[(size_t)NMAX * H];
__device__ __align__(16) float g_hid[(size_t)NMAX * H];
__device__ int   g_deg[NMAX];
__device__ float g_sumw[NMAX];
__device__ int   g_off[NMAX + 1];
__device__ int   g_cur[NMAX];
__device__ int   g_bsum[128];
__device__ int   g_csr[EMAX];

// ---------------- f32x2 helpers (sm_103a FFMA2) ----------------
__device__ __forceinline__ void ffma2(ull& d, ull a, ull b) {
    asm("fma.rn.f32x2 %0, %1, %2, %0;" : "+l"(d) : "l"(a), "l"(b));
}
__device__ __forceinline__ ull pk(float x, float y) {
    ull r; asm("mov.b64 %0, {%1, %2};" : "=l"(r) : "f"(x), "f"(y)); return r;
}
__device__ __forceinline__ float2 upk(ull v) {
    float2 f; asm("mov.b64 {%0, %1}, %2;" : "=f"(f.x), "=f"(f.y) : "l"(v)); return f;
}

// ---------------- CSR build ----------------
__global__ void k_zero(int n) {
    int i = blockIdx.x * blockDim.x + threadIdx.x;
    if (i < n) { g_deg[i] = 0; g_sumw[i] = 0.0f; }
    if (i < 128) g_bsum[i] = 0;
}

__global__ void k_hist(const int* __restrict__ ei, const float* __restrict__ ew, int E) {
    int e = blockIdx.x * blockDim.x + threadIdx.x;
    if (e >= E) return;
    int d = __ldg(ei + (size_t)E + e);
    atomicAdd(&g_deg[d], 1);
    atomicAdd(&g_sumw[d], __ldg(ew + e));
}

__global__ __launch_bounds__(1024) void k_scan1(int n) {
    __shared__ int sh[1024];
    int tid = threadIdx.x;
    int i = blockIdx.x * 1024 + tid;
    int v = (i < n) ? g_deg[i] : 0;
    sh[tid] = v;
    __syncthreads();
#pragma unroll
    for (int ofs = 1; ofs < 1024; ofs <<= 1) {
        int t = (tid >= ofs) ? sh[tid - ofs] : 0;
        __syncthreads();
        sh[tid] += t;
        __syncthreads();
    }
    if (i <= n) g_off[i] = sh[tid] - v;   // exclusive (within block)
    if (tid == 1023) g_bsum[blockIdx.x] = sh[1023];
}

__global__ void k_scan2() {
    __shared__ int sh[128];
    int tid = threadIdx.x;
    int v = g_bsum[tid];
    sh[tid] = v;
    __syncthreads();
#pragma unroll
    for (int ofs = 1; ofs < 128; ofs <<= 1) {
        int t = (tid >= ofs) ? sh[tid - ofs] : 0;
        __syncthreads();
        sh[tid] += t;
        __syncthreads();
    }
    g_bsum[tid] = sh[tid] - v;            // exclusive block bases
}

__global__ void k_scan3(int n, int E) {
    int i = blockIdx.x * blockDim.x + threadIdx.x;
    if (i < n) {
        int o = g_off[i] + g_bsum[i >> 10];
        g_off[i] = o;
        g_cur[i] = o;
    }
    if (i == 0) g_off[n] = E;
}

__global__ void k_fill(const int* __restrict__ ei, int E) {
    int e = blockIdx.x * blockDim.x + threadIdx.x;
    if (e >= E) return;
    int s = __ldg(ei + e);
    int d = __ldg(ei + (size_t)E + e);
    int pos = atomicAdd(&g_cur[d], 1);
    g_csr[pos] = s;
}

// ---------------- SpMM: agg[d] = x[d] + sum_{e->d} x[src] + sumw[d]*we + deg[d]*be
__global__ __launch_bounds__(256) void k_spmm(const float* __restrict__ x,
                                              const float* __restrict__ we,
                                              const float* __restrict__ be,
                                              int n) {
    int row = blockIdx.x * 8 + (threadIdx.x >> 5);
    int lane = threadIdx.x & 31;
    if (row >= n) return;

    float4 xr = __ldg((const float4*)(x + (size_t)row * H) + lane);
    float4 w4 = __ldg((const float4*)we + lane);
    float4 b4 = __ldg((const float4*)be + lane);
    float sw = __ldg(&g_sumw[row]);
    float dg = (float)__ldg(&g_deg[row]);

    float4 acc;
    acc.x = fmaf(sw, w4.x, fmaf(dg, b4.x, xr.x));
    acc.y = fmaf(sw, w4.y, fmaf(dg, b4.y, xr.y));
    acc.z = fmaf(sw, w4.z, fmaf(dg, b4.z, xr.z));
    acc.w = fmaf(sw, w4.w, fmaf(dg, b4.w, xr.w));

    int e = __ldg(&g_off[row]);
    int end = __ldg(&g_off[row + 1]);

    for (; e + 4 <= end; e += 4) {
        int s0 = __ldg(g_csr + e);
        int s1 = __ldg(g_csr + e + 1);
        int s2 = __ldg(g_csr + e + 2);
        int s3 = __ldg(g_csr + e + 3);
        float4 a0 = __ldg((const float4*)(x + (size_t)s0 * H) + lane);
        float4 a1 = __ldg((const float4*)(x + (size_t)s1 * H) + lane);
        float4 a2 = __ldg((const float4*)(x + (size_t)s2 * H) + lane);
        float4 a3 = __ldg((const float4*)(x + (size_t)s3 * H) + lane);
        acc.x += (a0.x + a1.x) + (a2.x + a3.x);
        acc.y += (a0.y + a1.y) + (a2.y + a3.y);
        acc.z += (a0.z + a1.z) + (a2.z + a3.z);
        acc.w += (a0.w + a1.w) + (a2.w + a3.w);
    }
    for (; e < end; ++e) {
        int s = __ldg(g_csr + e);
        float4 a = __ldg((const float4*)(x + (size_t)s * H) + lane);
        acc.x += a.x; acc.y += a.y; acc.z += a.z; acc.w += a.w;
    }
    ((float4*)(g_agg + (size_t)row * H))[lane] = acc;
}

// ---------------- MLP GEMM with FFMA2 ----------------
// C tile 64 rows x 128 cols, 256 threads, K in 4 chunks of 32.
// ws[k][col] fp32 (16KB); as_dup[row][k] duplicated-pair f32x2 (16KB).
template <bool RELU>
__device__ __forceinline__ void mlp_body(const float* __restrict__ in,
                                         const float* __restrict__ w,
                                         const float* __restrict__ bias,
                                         float* __restrict__ out, int n) {
    __shared__ float ws[32][H];          // 16 KB
    __shared__ ull as_dup[64][32];       // 16 KB (each entry = (a,a))

    int row0 = blockIdx.x * 64;
    int tid = threadIdx.x;
    int tr = tid >> 5;    // warp id 0..7 -> 8-row group
    int tc = tid & 31;    // lane -> 4-col group

    ull acc2[8][2];
#pragma unroll
    for (int r = 0; r < 8; ++r) { acc2[r][0] = 0ull; acc2[r][1] = 0ull; }

#pragma unroll
    for (int kc = 0; kc < 4; ++kc) {
        // stage W chunk: 128 cols x 8 float4 = 1024 float4, 4/thread
#pragma unroll
        for (int i = 0; i < 4; ++i) {
            int f4 = tid + 256 * i;
            int col = f4 & 127;
            int kq = f4 >> 7;   // 0..7
            float4 v = __ldg((const float4*)(w + (size_t)col * H + kc * 32) + kq);
            ws[kq * 4 + 0][col] = v.x;
            ws[kq * 4 + 1][col] = v.y;
            ws[kq * 4 + 2][col] = v.z;
            ws[kq * 4 + 3][col] = v.w;
        }
        // stage A chunk duplicated: 64 rows x 8 float4 = 512 float4, 2/thread
#pragma unroll
        for (int i = 0; i < 2; ++i) {
            int f4 = tid + 256 * i;
            int row = f4 >> 3;  // 0..63
            int kq = f4 & 7;    // 0..7
            int grow = row0 + row;
            float4 v = make_float4(0.f, 0.f, 0.f, 0.f);
            if (grow < n)
                v = __ldg((const float4*)(in + (size_t)grow * H + kc * 32) + kq);
            as_dup[row][kq * 4 + 0] = pk(v.x, v.x);
            as_dup[row][kq * 4 + 1] = pk(v.y, v.y);
            as_dup[row][kq * 4 + 2] = pk(v.z, v.z);
            as_dup[row][kq * 4 + 3] = pk(v.w, v.w);
        }
        __syncthreads();

#pragma unroll
        for (int k = 0; k < 32; ++k) {
            float4 b4 = ((float4*)ws[k])[tc];   // conflict-free LDS.128
            ull b01 = pk(b4.x, b4.y);
            ull b23 = pk(b4.z, b4.w);
#pragma unroll
            for (int r = 0; r < 8; ++r) {
                ull a2 = as_dup[tr * 8 + r][k];  // LDS.64 broadcast, pre-duplicated
                ffma2(acc2[r][0], a2, b01);
                ffma2(acc2[r][1], a2, b23);
            }
        }
        __syncthreads();
    }

    float4 bv = __ldg((const float4*)bias + tc);
#pragma unroll
    for (int r = 0; r < 8; ++r) {
        int grow = row0 + tr * 8 + r;
        if (grow < n) {
            float2 f01 = upk(acc2[r][0]);
            float2 f23 = upk(acc2[r][1]);
            float4 o;
            o.x = f01.x + bv.x;
            o.y = f01.y + bv.y;
            o.z = f23.x + bv.z;
            o.w = f23.y + bv.w;
            if (RELU) {
                o.x = fmaxf(o.x, 0.f);
                o.y = fmaxf(o.y, 0.f);
                o.z = fmaxf(o.z, 0.f);
                o.w = fmaxf(o.w, 0.f);
            }
            ((float4*)(out + (size_t)grow * H))[tc] = o;
        }
    }
}

__global__ __launch_bounds__(256) void mlp1_kernel(const float* __restrict__ w1,
                                                   const float* __restrict__ b1,
                                                   int n) {
    mlp_body<true>(g_agg, w1, b1, g_hid, n);
}

__global__ __launch_bounds__(256) void mlp2_kernel(const float* __restrict__ w2,
                                                   const float* __restrict__ b2,
                                                   float* __restrict__ out, int n) {
    mlp_body<false>(g_hid, w2, b2, out, n);
}

// ---------------- launch ----------------
// Inputs: 0:x[N,H] 1:edge_index[2,E]i32 2:edge_weight[E] 3:w_edge[H] 4:b_edge[H]
//         5:w1[H,H] 6:b1[H] 7:w2[H,H] 8:b2[H]   out:[N,H]f32
extern "C" void kernel_launch(void* const* d_in, const int* in_sizes, int n_in,
                              void* d_out, int out_size) {
    const float* x = (const float*)d_in[0];
    const int* ei = (const int*)d_in[1];
    const float* ew = (const float*)d_in[2];
    const float* w_edge = (const float*)d_in[3];
    const float* b_edge = (const float*)d_in[4];
    const float* w1 = (const float*)d_in[5];
    const float* b1 = (const float*)d_in[6];
    const float* w2 = (const float*)d_in[7];
    const float* b2 = (const float*)d_in[8];
    float* out = (float*)d_out;

    int n = in_sizes[0] / H;   // 100000
    int E = in_sizes[1] / 2;   // 1600000

    int eb = (E + 255) / 256;
    int nb = (n + 255) / 256;
    int sb = (n + 1023) / 1024;   // scan blocks (<=128)

    k_zero<<<nb, 256>>>(n);
    k_hist<<<eb, 256>>>(ei, ew, E);
    k_scan1<<<sb, 1024>>>(n);
    k_scan2<<<1, 128>>>();
    k_scan3<<<sb, 1024>>>(n, E);
    k_fill<<<eb, 256>>>(ei, E);
    k_spmm<<<(n + 7) / 8, 256>>>(x, w_edge, b_edge, n);

    int gblocks = (n + 63) / 64;
    mlp1_kernel<<<gblocks, 256>>>(w1, b1, n);
    mlp2_kernel<<<gblocks, 256>>>(w2, b2, out, n);
}

// round 4
// speedup vs baseline: 2.3601x; 1.7583x over previous
#include <cuda_runtime.h>

#define H 128
#define NMAX 100000
#define EMAX 1600000

// ---------------- device scratch (no allocs allowed) ----------------
__device__ __align__(16) float g_agg[(size_t)NMAX * H];
__device__ __align__(16) float g_hid[(size_t)NMAX * H];
__device__ int   g_deg[NMAX];
__device__ float g_sumw[NMAX];
__device__ int   g_off[NMAX + 1];
__device__ int   g_cur[NMAX];
__device__ int   g_bsum[128];
__device__ int   g_csr[EMAX];

// ---------------- CSR build ----------------
__global__ void k_zero(int n) {
    int i = blockIdx.x * blockDim.x + threadIdx.x;
    if (i < n) { g_deg[i] = 0; g_sumw[i] = 0.0f; }
    if (i < 128) g_bsum[i] = 0;
}

__global__ void k_hist(const int* __restrict__ ei, const float* __restrict__ ew, int E) {
    int e = blockIdx.x * blockDim.x + threadIdx.x;
    if (e >= E) return;
    int d = __ldg(ei + (size_t)E + e);
    atomicAdd(&g_deg[d], 1);
    atomicAdd(&g_sumw[d], __ldg(ew + e));
}

__global__ __launch_bounds__(1024) void k_scan1(int n) {
    __shared__ int sh[1024];
    int tid = threadIdx.x;
    int i = blockIdx.x * 1024 + tid;
    int v = (i < n) ? g_deg[i] : 0;
    sh[tid] = v;
    __syncthreads();
#pragma unroll
    for (int ofs = 1; ofs < 1024; ofs <<= 1) {
        int t = (tid >= ofs) ? sh[tid - ofs] : 0;
        __syncthreads();
        sh[tid] += t;
        __syncthreads();
    }
    if (i <= n) g_off[i] = sh[tid] - v;   // exclusive within block
    if (tid == 1023) g_bsum[blockIdx.x] = sh[1023];
}

// scan of per-block sums folded in: each block reduces its own base.
__global__ __launch_bounds__(1024) void k_scan3(int n, int E) {
    __shared__ int sh[128];
    __shared__ int s_base;
    int tid = threadIdx.x;
    int b = blockIdx.x;
    if (tid < 128) sh[tid] = (tid < b) ? g_bsum[tid] : 0;
    __syncthreads();
    if (tid < 64) sh[tid] += sh[tid + 64];
    __syncthreads();
    if (tid < 32) {
        int v = sh[tid] + sh[tid + 32];
#pragma unroll
        for (int o = 16; o > 0; o >>= 1) v += __shfl_down_sync(0xffffffffu, v, o);
        if (tid == 0) s_base = v;
    }
    __syncthreads();
    int base = s_base;
    int i = b * 1024 + tid;
    if (i < n) {
        int o = g_off[i] + base;
        g_off[i] = o;
        g_cur[i] = o;
    }
    if (i == 0) g_off[n] = E;
}

__global__ void k_fill(const int* __restrict__ ei, int E) {
    int e = blockIdx.x * blockDim.x + threadIdx.x;
    if (e >= E) return;
    int s = __ldg(ei + e);
    int d = __ldg(ei + (size_t)E + e);
    int pos = atomicAdd(&g_cur[d], 1);
    g_csr[pos] = s;
}

// ---------------- SpMM: agg[d] = x[d] + sum_{e->d} x[src] + sumw[d]*we + deg[d]*be
__global__ __launch_bounds__(256) void k_spmm(const float* __restrict__ x,
                                              const float* __restrict__ we,
                                              const float* __restrict__ be,
                                              int n) {
    int row = blockIdx.x * 8 + (threadIdx.x >> 5);
    int lane = threadIdx.x & 31;
    if (row >= n) return;

    float4 xr = __ldg((const float4*)(x + (size_t)row * H) + lane);
    float4 w4 = __ldg((const float4*)we + lane);
    float4 b4 = __ldg((const float4*)be + lane);
    float sw = __ldg(&g_sumw[row]);
    float dg = (float)__ldg(&g_deg[row]);

    float4 acc;
    acc.x = fmaf(sw, w4.x, fmaf(dg, b4.x, xr.x));
    acc.y = fmaf(sw, w4.y, fmaf(dg, b4.y, xr.y));
    acc.z = fmaf(sw, w4.z, fmaf(dg, b4.z, xr.z));
    acc.w = fmaf(sw, w4.w, fmaf(dg, b4.w, xr.w));

    int e = __ldg(&g_off[row]);
    int end = __ldg(&g_off[row + 1]);

    for (; e + 4 <= end; e += 4) {
        int s0 = __ldg(g_csr + e);
        int s1 = __ldg(g_csr + e + 1);
        int s2 = __ldg(g_csr + e + 2);
        int s3 = __ldg(g_csr + e + 3);
        float4 a0 = __ldg((const float4*)(x + (size_t)s0 * H) + lane);
        float4 a1 = __ldg((const float4*)(x + (size_t)s1 * H) + lane);
        float4 a2 = __ldg((const float4*)(x + (size_t)s2 * H) + lane);
        float4 a3 = __ldg((const float4*)(x + (size_t)s3 * H) + lane);
        acc.x += (a0.x + a1.x) + (a2.x + a3.x);
        acc.y += (a0.y + a1.y) + (a2.y + a3.y);
        acc.z += (a0.z + a1.z) + (a2.z + a3.z);
        acc.w += (a0.w + a1.w) + (a2.w + a3.w);
    }
    for (; e < end; ++e) {
        int s = __ldg(g_csr + e);
        float4 a = __ldg((const float4*)(x + (size_t)s * H) + lane);
        acc.x += a.x; acc.y += a.y; acc.z += a.z; acc.w += a.w;
    }
    ((float4*)(g_agg + (size_t)row * H))[lane] = acc;
}

// ---------------- tf32 tensor-core MLP GEMM ----------------
// out[m][o] = act( sum_k in[m][k] * w[o][k] + bias[o] )
// Block 256 thr: C tile 64 rows x 128 cols, K chunked x32.
// mma.m16n8k8 row.col: A(mxk) from as[row][k], B(kxn) = w[n][k] from ws[n][k].
// smem stride 36 floats -> (4n+k)%32 permutation => conflict-free frag loads.
#define KPAD 36

__device__ __forceinline__ unsigned f2tf(float f) {
    unsigned r; asm("cvt.rna.tf32.f32 %0, %1;" : "=r"(r) : "f"(f)); return r;
}

template <bool RELU>
__device__ __forceinline__ void mlp_body(const float* __restrict__ in,
                                         const float* __restrict__ w,
                                         const float* __restrict__ bias,
                                         float* __restrict__ out, int n) {
    __shared__ unsigned ws[128][KPAD];  // ws[n][k] tf32 bits (18.4 KB)
    __shared__ unsigned as[64][KPAD];   // as[row][k] tf32 bits (9.2 KB)

    int row0 = blockIdx.x * 64;
    int tid = threadIdx.x;
    int wid = tid >> 5;
    int lane = tid & 31;
    int g = lane >> 2;        // groupID 0..7
    int qt = lane & 3;        // thread-in-group 0..3
    int wm = wid & 3;         // row group (16 rows each)
    int wn = wid >> 2;        // col group (64 cols each)

    float acc[8][4];          // 8 n-tiles of m16n8 each
#pragma unroll
    for (int j = 0; j < 8; ++j)
#pragma unroll
        for (int c = 0; c < 4; ++c) acc[j][c] = 0.0f;

#pragma unroll
    for (int kc = 0; kc < 4; ++kc) {
        // stage W chunk: 128 n x 32 k = 1024 float4, 4 per thread
#pragma unroll
        for (int i = 0; i < 4; ++i) {
            int f4 = tid + 256 * i;
            int col = f4 >> 3;       // n 0..127
            int kq = f4 & 7;         // 0..7
            float4 v = __ldg((const float4*)(w + (size_t)col * H + kc * 32) + kq);
            ws[col][kq * 4 + 0] = f2tf(v.x);
            ws[col][kq * 4 + 1] = f2tf(v.y);
            ws[col][kq * 4 + 2] = f2tf(v.z);
            ws[col][kq * 4 + 3] = f2tf(v.w);
        }
        // stage A chunk: 64 rows x 32 k = 512 float4, 2 per thread
#pragma unroll
        for (int i = 0; i < 2; ++i) {
            int f4 = tid + 256 * i;
            int row = f4 >> 3;       // 0..63
            int kq = f4 & 7;
            int grow = row0 + row;
            float4 v = make_float4(0.f, 0.f, 0.f, 0.f);
            if (grow < n)
                v = __ldg((const float4*)(in + (size_t)grow * H + kc * 32) + kq);
            as[row][kq * 4 + 0] = f2tf(v.x);
            as[row][kq * 4 + 1] = f2tf(v.y);
            as[row][kq * 4 + 2] = f2tf(v.z);
            as[row][kq * 4 + 3] = f2tf(v.w);
        }
        __syncthreads();

#pragma unroll
        for (int kk = 0; kk < 4; ++kk) {
            int k0 = kk * 8;
            unsigned a0 = as[wm * 16 + g][k0 + qt];
            unsigned a1 = as[wm * 16 + g + 8][k0 + qt];
            unsigned a2 = as[wm * 16 + g][k0 + qt + 4];
            unsigned a3 = as[wm * 16 + g + 8][k0 + qt + 4];
#pragma unroll
            for (int j = 0; j < 8; ++j) {
                int nb = wn * 64 + j * 8;
                unsigned b0 = ws[nb + g][k0 + qt];
                unsigned b1 = ws[nb + g][k0 + qt + 4];
                asm volatile(
                    "mma.sync.aligned.m16n8k8.row.col.f32.tf32.tf32.f32 "
                    "{%0,%1,%2,%3}, {%4,%5,%6,%7}, {%8,%9}, {%0,%1,%2,%3};"
                    : "+f"(acc[j][0]), "+f"(acc[j][1]), "+f"(acc[j][2]), "+f"(acc[j][3])
                    : "r"(a0), "r"(a1), "r"(a2), "r"(a3), "r"(b0), "r"(b1));
            }
        }
        __syncthreads();
    }

    // epilogue: c0,c1 at (row g, cols 2qt,2qt+1); c2,c3 at row g+8.
    int r0 = row0 + wm * 16 + g;
    int r1 = r0 + 8;
#pragma unroll
    for (int j = 0; j < 8; ++j) {
        int col0 = wn * 64 + j * 8 + qt * 2;
        float2 bv = __ldg((const float2*)(bias + col0));
        float2 o0, o1;
        o0.x = acc[j][0] + bv.x; o0.y = acc[j][1] + bv.y;
        o1.x = acc[j][2] + bv.x; o1.y = acc[j][3] + bv.y;
        if (RELU) {
            o0.x = fmaxf(o0.x, 0.f); o0.y = fmaxf(o0.y, 0.f);
            o1.x = fmaxf(o1.x, 0.f); o1.y = fmaxf(o1.y, 0.f);
        }
        if (r0 < n) *(float2*)(out + (size_t)r0 * H + col0) = o0;
        if (r1 < n) *(float2*)(out + (size_t)r1 * H + col0) = o1;
    }
}

__global__ __launch_bounds__(256) void mlp1_kernel(const float* __restrict__ w1,
                                                   const float* __restrict__ b1,
                                                   int n) {
    mlp_body<true>(g_agg, w1, b1, g_hid, n);
}

__global__ __launch_bounds__(256) void mlp2_kernel(const float* __restrict__ w2,
                                                   const float* __restrict__ b2,
                                                   float* __restrict__ out, int n) {
    mlp_body<false>(g_hid, w2, b2, out, n);
}

// ---------------- launch ----------------
// Inputs: 0:x[N,H] 1:edge_index[2,E]i32 2:edge_weight[E] 3:w_edge[H] 4:b_edge[H]
//         5:w1[H,H] 6:b1[H] 7:w2[H,H] 8:b2[H]   out:[N,H]f32
extern "C" void kernel_launch(void* const* d_in, const int* in_sizes, int n_in,
                              void* d_out, int out_size) {
    const float* x = (const float*)d_in[0];
    const int* ei = (const int*)d_in[1];
    const float* ew = (const float*)d_in[2];
    const float* w_edge = (const float*)d_in[3];
    const float* b_edge = (const float*)d_in[4];
    const float* w1 = (const float*)d_in[5];
    const float* b1 = (const float*)d_in[6];
    const float* w2 = (const float*)d_in[7];
    const float* b2 = (const float*)d_in[8];
    float* out = (float*)d_out;

    int n = in_sizes[0] / H;   // 100000
    int E = in_sizes[1] / 2;   // 1600000

    int eb = (E + 255) / 256;
    int nb = (n + 255) / 256;
    int sb = (n + 1023) / 1024;   // scan blocks (<=128)

    k_zero<<<nb, 256>>>(n);
    k_hist<<<eb, 256>>>(ei, ew, E);
    k_scan1<<<sb, 1024>>>(n);
    k_scan3<<<sb, 1024>>>(n, E);
    k_fill<<<eb, 256>>>(ei, E);
    k_spmm<<<(n + 7) / 8, 256>>>(x, w_edge, b_edge, n);

    int gblocks = (n + 63) / 64;
    mlp1_kernel<<<gblocks, 256>>>(w1, b1, n);
    mlp2_kernel<<<gblocks, 256>>>(w2, b2, out, n);
}

// round 5
// speedup vs baseline: 2.5193x; 1.0674x over previous
#include <cuda_runtime.h>

#define H 128
#define NMAX 100000
#define EMAX 1600000

typedef unsigned long long ull;

// ---------------- device scratch (no allocs allowed) ----------------
__device__ ull   g_degsum[NMAX];     // [deg:16][sumw_fixed(2^-32):48]
__device__ int   g_off[NMAX + 1];
__device__ int   g_cur[NMAX];
__device__ int   g_bsum[128];
__device__ int   g_csr[EMAX];

__device__ __forceinline__ unsigned f2tf(float f) {
    unsigned r; asm("cvt.rna.tf32.f32 %0, %1;" : "=r"(r) : "f"(f)); return r;
}

// ---------------- CSR build ----------------
__global__ void k_zero(int n) {
    int i = blockIdx.x * blockDim.x + threadIdx.x;
    if (i < n) g_degsum[i] = 0ull;
}

__global__ void k_hist(const int* __restrict__ ei, const float* __restrict__ ew, int E) {
    int e = blockIdx.x * blockDim.x + threadIdx.x;
    if (e >= E) return;
    int d = __ldg(ei + (size_t)E + e);
    float w = __ldg(ew + e);
    // pack: deg increment in bits[48:], sumw in 2^-32 fixed point in bits[:48]
    ull v = (1ull << 48) + (ull)(w * 4294967296.0f);
    atomicAdd(&g_degsum[d], v);
}

__global__ __launch_bounds__(1024) void k_scan1(int n) {
    __shared__ int sh[1024];
    int tid = threadIdx.x;
    int i = blockIdx.x * 1024 + tid;
    int v = (i < n) ? (int)(g_degsum[i] >> 48) : 0;
    sh[tid] = v;
    __syncthreads();
#pragma unroll
    for (int ofs = 1; ofs < 1024; ofs <<= 1) {
        int t = (tid >= ofs) ? sh[tid - ofs] : 0;
        __syncthreads();
        sh[tid] += t;
        __syncthreads();
    }
    if (i <= n) g_off[i] = sh[tid] - v;   // exclusive within block
    if (tid == 1023) g_bsum[blockIdx.x] = sh[1023];
}

// fold block-base scan into the apply pass (each block reduces its own base)
__global__ __launch_bounds__(1024) void k_scan3(int n, int E) {
    __shared__ int sh[128];
    __shared__ int s_base;
    int tid = threadIdx.x;
    int b = blockIdx.x;
    if (tid < 128) sh[tid] = (tid < b) ? g_bsum[tid] : 0;
    __syncthreads();
    if (tid < 64) sh[tid] += sh[tid + 64];
    __syncthreads();
    if (tid < 32) {
        int v = sh[tid] + sh[tid + 32];
#pragma unroll
        for (int o = 16; o > 0; o >>= 1) v += __shfl_down_sync(0xffffffffu, v, o);
        if (tid == 0) s_base = v;
    }
    __syncthreads();
    int base = s_base;
    int i = b * 1024 + tid;
    if (i < n) {
        int o = g_off[i] + base;
        g_off[i] = o;
        g_cur[i] = o;
    }
    if (i == 0) g_off[n] = E;
}

__global__ void k_fill(const int* __restrict__ ei, int E) {
    int e = blockIdx.x * blockDim.x + threadIdx.x;
    if (e >= E) return;
    int s = __ldg(ei + e);
    int d = __ldg(ei + (size_t)E + e);
    int pos = atomicAdd(&g_cur[d], 1);
    g_csr[pos] = s;
}

// ---------------- fused SpMM + MLP1 + MLP2 ----------------
// Block handles 64 rows. Phase 0: gather agg rows -> smem tf32 (stride 132).
// Phase 1: GEMM1 (w1, relu) -> smem tf32. Phase 2: GEMM2 (w2) -> out.
#define KW 16     // k-chunk width for W staging
#define WSP 20    // ws stride (floats): (20g+qt)%32 spans all banks
#define ASP 132   // A stride (floats): 132%32=4 -> (4g+qt)%32 spans all banks

struct SmemT {
    __align__(16) unsigned as_f[64][ASP];   // 33.8 KB: agg tile, then hid tile
    __align__(16) unsigned ws[128][WSP];    // 10.2 KB: current W chunk
};

// One 64x128 GEMM over K=128 from as_f, W staged per 16-k chunk.
template <bool RELU, bool TO_SMEM>
__device__ __forceinline__ void gemm_tile(SmemT* sm,
                                          const float* __restrict__ w,
                                          const float* __restrict__ bias,
                                          float* __restrict__ out,
                                          int row0, int n, int tid) {
    int wid = tid >> 5;
    int lane = tid & 31;
    int g = lane >> 2;      // 0..7
    int qt = lane & 3;      // 0..3
    int wm = wid & 3;       // 16-row group
    int wn = wid >> 2;      // 64-col group

    float acc[8][4];
#pragma unroll
    for (int j = 0; j < 8; ++j)
#pragma unroll
        for (int c = 0; c < 4; ++c) acc[j][c] = 0.0f;

#pragma unroll
    for (int kc = 0; kc < 8; ++kc) {
        // stage W chunk: 128 cols x 16 k = 512 float4, 2 per thread
#pragma unroll
        for (int i = 0; i < 2; ++i) {
            int f4 = tid + 256 * i;
            int col = f4 >> 2;       // 0..127
            int kq = f4 & 3;         // 0..3
            float4 v = __ldg((const float4*)(w + (size_t)col * H + kc * KW) + kq);
            uint4 t;
            t.x = f2tf(v.x); t.y = f2tf(v.y); t.z = f2tf(v.z); t.w = f2tf(v.w);
            *(uint4*)&sm->ws[col][kq * 4] = t;
        }
        __syncthreads();

#pragma unroll
        for (int kk = 0; kk < 2; ++kk) {
            int k0 = kk * 8;
            int ka = kc * KW + k0;
            unsigned a0 = sm->as_f[wm * 16 + g][ka + qt];
            unsigned a1 = sm->as_f[wm * 16 + g + 8][ka + qt];
            unsigned a2 = sm->as_f[wm * 16 + g][ka + qt + 4];
            unsigned a3 = sm->as_f[wm * 16 + g + 8][ka + qt + 4];
#pragma unroll
            for (int j = 0; j < 8; ++j) {
                int nb = wn * 64 + j * 8;
                unsigned b0 = sm->ws[nb + g][k0 + qt];
                unsigned b1 = sm->ws[nb + g][k0 + qt + 4];
                asm volatile(
                    "mma.sync.aligned.m16n8k8.row.col.f32.tf32.tf32.f32 "
                    "{%0,%1,%2,%3}, {%4,%5,%6,%7}, {%8,%9}, {%0,%1,%2,%3};"
                    : "+f"(acc[j][0]), "+f"(acc[j][1]), "+f"(acc[j][2]), "+f"(acc[j][3])
                    : "r"(a0), "r"(a1), "r"(a2), "r"(a3), "r"(b0), "r"(b1));
            }
        }
        __syncthreads();   // ws reused next chunk; also protects as_f overwrite below
    }

    int r0l = wm * 16 + g;
    int r1l = r0l + 8;
#pragma unroll
    for (int j = 0; j < 8; ++j) {
        int col0 = wn * 64 + j * 8 + qt * 2;
        float2 bv = __ldg((const float2*)(bias + col0));
        float2 o0, o1;
        o0.x = acc[j][0] + bv.x; o0.y = acc[j][1] + bv.y;
        o1.x = acc[j][2] + bv.x; o1.y = acc[j][3] + bv.y;
        if (RELU) {
            o0.x = fmaxf(o0.x, 0.f); o0.y = fmaxf(o0.y, 0.f);
            o1.x = fmaxf(o1.x, 0.f); o1.y = fmaxf(o1.y, 0.f);
        }
        if (TO_SMEM) {
            uint2 t0, t1;
            t0.x = f2tf(o0.x); t0.y = f2tf(o0.y);
            t1.x = f2tf(o1.x); t1.y = f2tf(o1.y);
            *(uint2*)&sm->as_f[r0l][col0] = t0;
            *(uint2*)&sm->as_f[r1l][col0] = t1;
        } else {
            int gr0 = row0 + r0l, gr1 = row0 + r1l;
            if (gr0 < n) *(float2*)(out + (size_t)gr0 * H + col0) = o0;
            if (gr1 < n) *(float2*)(out + (size_t)gr1 * H + col0) = o1;
        }
    }
}

__global__ __launch_bounds__(256) void k_fused(const float* __restrict__ x,
                                               const float* __restrict__ we,
                                               const float* __restrict__ be,
                                               const float* __restrict__ w1,
                                               const float* __restrict__ b1,
                                               const float* __restrict__ w2,
                                               const float* __restrict__ b2,
                                               float* __restrict__ out, int n) {
    __shared__ SmemT sm;

    int row0 = blockIdx.x * 64;
    int tid = threadIdx.x;
    int wid = tid >> 5;
    int lane = tid & 31;

    // ---- Phase 0: gather agg rows into as_f (tf32) ----
    float4 w4 = __ldg((const float4*)we + lane);
    float4 b4 = __ldg((const float4*)be + lane);

#pragma unroll 1
    for (int i = 0; i < 8; ++i) {
        int lr = wid * 8 + i;
        int row = row0 + lr;
        float4 acc = make_float4(0.f, 0.f, 0.f, 0.f);
        if (row < n) {
            float4 xr = __ldg((const float4*)(x + (size_t)row * H) + lane);
            ull ps = __ldg(&g_degsum[row]);
            float dg = (float)(unsigned)(ps >> 48);
            float sw = (float)(ps & 0xFFFFFFFFFFFFull) * (1.0f / 4294967296.0f);

            acc.x = fmaf(sw, w4.x, fmaf(dg, b4.x, xr.x));
            acc.y = fmaf(sw, w4.y, fmaf(dg, b4.y, xr.y));
            acc.z = fmaf(sw, w4.z, fmaf(dg, b4.z, xr.z));
            acc.w = fmaf(sw, w4.w, fmaf(dg, b4.w, xr.w));

            int e = __ldg(&g_off[row]);
            int end = __ldg(&g_off[row + 1]);
            for (; e + 4 <= end; e += 4) {
                int s0 = __ldg(g_csr + e);
                int s1 = __ldg(g_csr + e + 1);
                int s2 = __ldg(g_csr + e + 2);
                int s3 = __ldg(g_csr + e + 3);
                float4 a0 = __ldg((const float4*)(x + (size_t)s0 * H) + lane);
                float4 a1 = __ldg((const float4*)(x + (size_t)s1 * H) + lane);
                float4 a2 = __ldg((const float4*)(x + (size_t)s2 * H) + lane);
                float4 a3 = __ldg((const float4*)(x + (size_t)s3 * H) + lane);
                acc.x += (a0.x + a1.x) + (a2.x + a3.x);
                acc.y += (a0.y + a1.y) + (a2.y + a3.y);
                acc.z += (a0.z + a1.z) + (a2.z + a3.z);
                acc.w += (a0.w + a1.w) + (a2.w + a3.w);
            }
            for (; e < end; ++e) {
                int s = __ldg(g_csr + e);
                float4 a = __ldg((const float4*)(x + (size_t)s * H) + lane);
                acc.x += a.x; acc.y += a.y; acc.z += a.z; acc.w += a.w;
            }
        }
        uint4 t;
        t.x = f2tf(acc.x); t.y = f2tf(acc.y); t.z = f2tf(acc.z); t.w = f2tf(acc.w);
        *(uint4*)&sm.as_f[lr][lane * 4] = t;
    }
    __syncthreads();

    // ---- Phase 1: hid = relu(agg @ w1^T + b1) -> as_f ----
    gemm_tile<true, true>(&sm, w1, b1, nullptr, row0, n, tid);
    __syncthreads();

    // ---- Phase 2: out = hid @ w2^T + b2 ----
    gemm_tile<false, false>(&sm, w2, b2, out, row0, n, tid);
}

// ---------------- launch ----------------
// Inputs: 0:x[N,H] 1:edge_index[2,E]i32 2:edge_weight[E] 3:w_edge[H] 4:b_edge[H]
//         5:w1[H,H] 6:b1[H] 7:w2[H,H] 8:b2[H]   out:[N,H]f32
extern "C" void kernel_launch(void* const* d_in, const int* in_sizes, int n_in,
                              void* d_out, int out_size) {
    const float* x = (const float*)d_in[0];
    const int* ei = (const int*)d_in[1];
    const float* ew = (const float*)d_in[2];
    const float* w_edge = (const float*)d_in[3];
    const float* b_edge = (const float*)d_in[4];
    const float* w1 = (const float*)d_in[5];
    const float* b1 = (const float*)d_in[6];
    const float* w2 = (const float*)d_in[7];
    const float* b2 = (const float*)d_in[8];
    float* out = (float*)d_out;

    int n = in_sizes[0] / H;   // 100000
    int E = in_sizes[1] / 2;   // 1600000

    int eb = (E + 255) / 256;
    int nb = (n + 255) / 256;
    int sb = (n + 1023) / 1024;   // <=128 scan blocks

    k_zero<<<nb, 256>>>(n);
    k_hist<<<eb, 256>>>(ei, ew, E);
    k_scan1<<<sb, 1024>>>(n);
    k_scan3<<<sb, 1024>>>(n, E);
    k_fill<<<eb, 256>>>(ei, E);
    k_fused<<<(n + 63) / 64, 256>>>(x, w_edge, b_edge, w1, b1, w2, b2, out, n);
}